// round 15
// baseline (speedup 1.0000x reference)
#include <cuda_runtime.h>
#include <cuda_fp16.h>

// ---------------------------------------------------------------------------
// GSOrthogonal round 15: stage1 as tiny independent CTAs (64 thr, one-shot
// 32x64x64 GEMM, 16 CTAs/SM) to attack the per-CTA serialization. Stage2 +
// cayley identical to round 14. Stages split into 2 launches each so the
// fixed ncu capture window (-s 5 -c 1) can land on a stage kernel.
//  stage1: g_t[l][r][b] = sum_p Rq[r][l][p] x[b][r*64+p]
//  stage2: y[b][s*64+l] = sum_r Lq[l][s][r] t[l][r][b]
// ---------------------------------------------------------------------------

__device__ __half g_Lq[64 * 64 * 64];
__device__ __half g_Rq[64 * 64 * 64];
__device__ __half g_t[(size_t)4096 * 16384];     // [l][r][b] fp16

__device__ __forceinline__ unsigned smem_u32(const void* p) {
    unsigned a;
    asm("{ .reg .u64 t; cvta.to.shared.u64 t, %1; cvt.u32.u64 %0, t; }"
        : "=r"(a) : "l"(p));
    return a;
}

#define SWZ(o) ((o) ^ (((o) >> 3) & 0x70u))

#define LDSM4(r0, r1, r2, r3, addr)                                           \
    asm volatile("ldmatrix.sync.aligned.m8n8.x4.shared.b16 {%0,%1,%2,%3},[%4];" \
        : "=r"(r0), "=r"(r1), "=r"(r2), "=r"(r3) : "r"(addr))
#define LDSM4T(r0, r1, r2, r3, addr)                                          \
    asm volatile("ldmatrix.sync.aligned.m8n8.x4.trans.shared.b16 {%0,%1,%2,%3},[%4];" \
        : "=r"(r0), "=r"(r1), "=r"(r2), "=r"(r3) : "r"(addr))
#define MMAF(d, a, b0, b1)                                                    \
    asm volatile("mma.sync.aligned.m16n8k16.row.col.f32.f16.f16.f32 "         \
        "{%0,%1,%2,%3},{%4,%5,%6,%7},{%8,%9},{%0,%1,%2,%3};"                  \
        : "+f"((d)[0]), "+f"((d)[1]), "+f"((d)[2]), "+f"((d)[3])              \
        : "r"((a)[0]), "r"((a)[1]), "r"((a)[2]), "r"((a)[3]), "r"(b0), "r"(b1))

__device__ __forceinline__ unsigned pack2h(__half a, __half b) {
    return (unsigned)__half_as_ushort(a) | ((unsigned)__half_as_ushort(b) << 16);
}

// ---------------- Cayley: scale-free GJ inverse, register-blocked -----------
#define CLD 68
__global__ __launch_bounds__(32) void cayley_kernel(
    const float* __restrict__ Lin, const float* __restrict__ Rin) {
    __shared__ float C[64 * CLD];
    const int blk = blockIdx.x;
    const float* A = blk < 64 ? Lin + blk * 4096 : Rin + (blk - 64) * 4096;
    __half* Q = blk < 64 ? g_Lq + blk * 4096 : g_Rq + (blk - 64) * 4096;
    const int lane = threadIdx.x;
    const int r0 = lane, r1 = lane + 32;

    for (int e = lane; e < 4096; e += 32) {
        int i = e >> 6, j = e & 63;
        C[i * CLD + j] = ((i == j) ? 1.0f : 0.0f)
                       + 0.5f * (A[i * 64 + j] - A[j * 64 + i]);
    }
    __syncwarp();

    for (int k = 0; k < 64; k++) {
        float piv = __fdividef(1.0f, C[k * CLD + k]);
        float f0 = C[r0 * CLD + k] * piv;
        float f1 = C[r1 * CLD + k] * piv;
        bool u0 = (r0 != k), u1 = (r1 != k);
        __syncwarp();
        #pragma unroll
        for (int h = 0; h < 2; h++) {
            const float4* p4 = (const float4*)(C + k * CLD) + h * 8;
            float4* m0 = (float4*)(C + r0 * CLD) + h * 8;
            float4* m1 = (float4*)(C + r1 * CLD) + h * 8;
            float4 p[8], a[8], b[8];
            #pragma unroll
            for (int c = 0; c < 8; c++) p[c] = p4[c];
            #pragma unroll
            for (int c = 0; c < 8; c++) a[c] = m0[c];
            #pragma unroll
            for (int c = 0; c < 8; c++) b[c] = m1[c];
            #pragma unroll
            for (int c = 0; c < 8; c++) {
                a[c].x -= f0 * p[c].x; a[c].y -= f0 * p[c].y;
                a[c].z -= f0 * p[c].z; a[c].w -= f0 * p[c].w;
                b[c].x -= f1 * p[c].x; b[c].y -= f1 * p[c].y;
                b[c].z -= f1 * p[c].z; b[c].w -= f1 * p[c].w;
            }
            if (u0) {
                #pragma unroll
                for (int c = 0; c < 8; c++) m0[c] = a[c];
            }
            if (u1) {
                #pragma unroll
                for (int c = 0; c < 8; c++) m1[c] = b[c];
            }
        }
        if (u0) C[r0 * CLD + k] = -f0;
        else  { C[r0 * CLD + k] = 1.0f; C[r0 * CLD + 64] = piv; }
        if (u1) C[r1 * CLD + k] = -f1;
        else  { C[r1 * CLD + k] = 1.0f; C[r1 * CLD + 64] = piv; }
        __syncwarp();
    }

    for (int e = lane; e < 4096; e += 32) {
        int a = e >> 6, b = e & 63;
        float v = 2.0f * C[b * CLD + 64] * C[b * CLD + a] - (a == b ? 1.0f : 0.0f);
        Q[e] = __float2half_rn(v);
    }
}

// ---------------- Stage 1: tiny CTA (64 thr), one-shot 32x64x64 GEMM --------
// smem: A 32x128B @0 (4KB); B 64x128B @4096 (8KB). 16 CTAs/SM target.
#define S1_A   0
#define S1_B   4096
#define S1_SMEM 12288

__global__ __launch_bounds__(64) void stage1_kernel(const float* __restrict__ x,
                                                    int ybase) {
    extern __shared__ char sm[];
    const unsigned sb = smem_u32(sm);
    const int tid = threadIdx.x, wid = tid >> 5, lane = tid & 31;
    const int rblk = blockIdx.x;
    const long b0 = (long)(ybase + blockIdx.y) * 32;

    // B = Rq[rblk] 64x64 fp16 (L2-hot; redundant across b-tiles)
    #pragma unroll
    for (int q = 0; q < 16; q++) {
        int f = q * 64 + tid;                     // 0..1023
        int row = f >> 4, c4 = f & 15;
        uint2 u = *(const uint2*)(g_Rq + (size_t)rblk * 4096 + f * 4);
        *(uint2*)(sm + S1_B + SWZ((unsigned)(row * 128 + c4 * 8))) = u;
    }
    // A = x tile 32x64, converted to fp16
    #pragma unroll
    for (int q = 0; q < 8; q++) {
        int f = q * 64 + tid;                     // 0..511
        int row = f >> 4, p4 = f & 15;
        float4 v = *(const float4*)(x + (b0 + row) * 4096 + rblk * 64 + p4 * 4);
        uint2 h = make_uint2(pack2h(__float2half_rn(v.x), __float2half_rn(v.y)),
                             pack2h(__float2half_rn(v.z), __float2half_rn(v.w)));
        *(uint2*)(sm + S1_A + SWZ((unsigned)(row * 128 + p4 * 8))) = h;
    }
    __syncthreads();

    // warp w: rows M0..M0+15, all 64 l-cols
    const int M0 = wid * 16;
    float acc[8][4] = {};
    #pragma unroll
    for (int kk = 0; kk < 4; kk++) {
        unsigned a4[4];
        {
            unsigned row = M0 + (lane & 15);
            unsigned ph = SWZ(row * 128 + kk * 32 + ((lane >> 4) << 4));
            LDSM4(a4[0], a4[1], a4[2], a4[3], sb + S1_A + ph);
        }
        #pragma unroll
        for (int nh = 0; nh < 4; nh++) {
            unsigned brow = nh * 16 + (lane & 7) + ((lane >> 4) << 3);
            unsigned bph = SWZ(brow * 128 + kk * 32 + (((lane >> 3) & 1) << 4));
            unsigned b4[4];
            LDSM4(b4[0], b4[1], b4[2], b4[3], sb + S1_B + bph);
            MMAF(acc[nh * 2 + 0], a4, b4[0], b4[1]);
            MMAF(acc[nh * 2 + 1], a4, b4[2], b4[3]);
        }
    }

    // epilogue: fp16 stores to g_t[l][r][b]  (acc[j] covers l-cols j*8..j*8+7)
    const int g = lane >> 2, t2 = (lane & 3) << 1;
    const long bb = b0 + M0 + g;
    #pragma unroll
    for (int nt = 0; nt < 8; nt++) {
        int l0 = nt * 8 + t2;
        size_t base = ((size_t)l0 * 64 + rblk) * 16384;
        g_t[base + bb]               = __float2half_rn(acc[nt][0]);
        g_t[base + 1048576 + bb]     = __float2half_rn(acc[nt][1]);   // l0+1
        g_t[base + bb + 8]           = __float2half_rn(acc[nt][2]);
        g_t[base + 1048576 + bb + 8] = __float2half_rn(acc[nt][3]);
    }
}

// ---------------- Stage 2: 2 b-tiles x 4 l's, hoisted W frags (= round 14) --
#define S2_AT0 0
#define S2_AT1 8192
#define S2_OS  16384
#define S2_W   16384
#define S2_SMEM (16384 + 4 * 4224 * 4)        // 83968
#define S2_TILES 2

__global__ __launch_bounds__(256, 2) void stage2_kernel(float* __restrict__ y,
                                                        int ybase) {
    extern __shared__ char sm[];
    const unsigned sb = smem_u32(sm);
    float* os = (float*)(sm + S2_OS);
    const int tid = threadIdx.x, wid = tid >> 5, lane = tid & 31;
    const int lg = blockIdx.x;                    // 0..15
    const long bbase = (long)(ybase + blockIdx.y) * (64 * S2_TILES);

    const int wm = wid & 1, wn = wid >> 1;        // warp tile m32 x n16
    const int M0 = wm * 32, N0 = wn * 16;
    const int g = lane >> 2, t2 = (lane & 3) << 1;

    // W planes -> smem (overlay region), once
    #pragma unroll
    for (int q = 0; q < 16; q++) {
        int f = q * 256 + tid;                    // 0..4095
        int pl = f >> 10, e = f & 1023;
        int r = e >> 4, b4 = e & 15;
        uint2 u = *(const uint2*)(g_Lq + (size_t)(lg * 4 + pl) * 4096 + e * 4);
        *(uint2*)(sm + S2_W + pl * 8192 + SWZ((unsigned)(r * 128 + b4 * 8))) = u;
    }
    // prefetch A (iter 0)
    uint2 abuf[4];
    #pragma unroll
    for (int q = 0; q < 4; q++) {
        int f = q * 256 + tid;
        int r = f >> 4, b4 = f & 15;
        abuf[q] = *(const uint2*)(g_t + ((size_t)(lg * 4) * 64 + r) * 16384
                                      + bbase + b4 * 4);
    }
    __syncthreads();

    // hoist ALL W fragments (4 planes x 4 kk), reused across both b-tiles
    unsigned wfr[4][4][4];
    #pragma unroll
    for (int ll = 0; ll < 4; ll++)
        #pragma unroll
        for (int kk = 0; kk < 4; kk++) {
            unsigned row = N0 + (lane & 7) + ((lane >> 4) << 3);
            unsigned ph = SWZ(row * 128 + kk * 32 + (((lane >> 3) & 1) << 4));
            LDSM4(wfr[ll][kk][0], wfr[ll][kk][1], wfr[ll][kk][2], wfr[ll][kk][3],
                  sb + S2_W + ll * 8192 + ph);
        }

    for (int tbi = 0; tbi < S2_TILES; tbi++) {
        const long b0 = bbase + tbi * 64;
        for (int ll = 0; ll < 4; ll++) {
            const int iter = tbi * 4 + ll;
            const unsigned atb = sb + ((iter & 1) ? S2_AT1 : S2_AT0);
            #pragma unroll
            for (int q = 0; q < 4; q++) {
                int f = q * 256 + tid;
                int r = f >> 4, b4 = f & 15;
                *(uint2*)(sm + ((iter & 1) ? S2_AT1 : S2_AT0)
                          + SWZ((unsigned)(r * 128 + b4 * 8))) = abuf[q];
            }
            __syncthreads();
            if (iter + 1 < S2_TILES * 4) {
                int tn = (iter + 1) >> 2, ln = (iter + 1) & 3;
                const long bn = bbase + tn * 64;
                #pragma unroll
                for (int q = 0; q < 4; q++) {
                    int f = q * 256 + tid;
                    int r = f >> 4, b4 = f & 15;
                    abuf[q] = *(const uint2*)(g_t
                        + ((size_t)(lg * 4 + ln) * 64 + r) * 16384 + bn + b4 * 4);
                }
            }

            float acc[2][2][4] = {};
            #pragma unroll
            for (int kk = 0; kk < 4; kk++) {
                unsigned ah[2][4];
                #pragma unroll
                for (int mt = 0; mt < 2; mt++) {   // A via ldmatrix.trans
                    unsigned row = kk * 16 + (lane & 7) + ((lane >> 4) << 3);
                    unsigned cb = (M0 + mt * 16 + (((lane >> 3) & 1) << 3)) * 2;
                    unsigned ph = SWZ(row * 128 + cb);
                    LDSM4T(ah[mt][0], ah[mt][1], ah[mt][2], ah[mt][3], atb + ph);
                }
                #pragma unroll
                for (int mt = 0; mt < 2; mt++) {
                    MMAF(acc[mt][0], ah[mt], wfr[ll][kk][0], wfr[ll][kk][1]);
                    MMAF(acc[mt][1], ah[mt], wfr[ll][kk][2], wfr[ll][kk][3]);
                }
            }

            #pragma unroll
            for (int mt = 0; mt < 2; mt++)
                #pragma unroll
                for (int nt = 0; nt < 2; nt++) {
                    float* p = os + ll * 4224 + (M0 + mt * 16 + g) * 66
                                  + N0 + nt * 8 + t2;
                    *(float2*)p = make_float2(acc[mt][nt][0], acc[mt][nt][1]);
                    *(float2*)(p + 8 * 66) = make_float2(acc[mt][nt][2],
                                                         acc[mt][nt][3]);
                }
        }
        __syncthreads();   // all os planes visible

        for (int e = tid; e < 4096; e += 256) {
            int b = e >> 6, s = e & 63;
            int idx = b * 66 + s;
            float4 v = make_float4(os[idx], os[4224 + idx],
                                   os[8448 + idx], os[12672 + idx]);
            *(float4*)(y + (b0 + b) * 4096 + s * 64 + lg * 4) = v;
        }
    }
}

// ---------------------------------------------------------------------------
extern "C" void kernel_launch(void* const* d_in, const int* in_sizes, int n_in,
                              void* d_out, int out_size) {
    const float* x = (const float*)d_in[0];
    const float* L = (const float*)d_in[1];
    const float* R = (const float*)d_in[2];
    float* y = (float*)d_out;

    cudaFuncSetAttribute(stage1_kernel,
                         cudaFuncAttributeMaxDynamicSharedMemorySize, S1_SMEM);
    cudaFuncSetAttribute(stage2_kernel,
                         cudaFuncAttributeMaxDynamicSharedMemorySize, S2_SMEM);

    cayley_kernel<<<128, 32>>>(L, R);
    // stages split into half-grids: shifts the ncu capture window (-s 5 -c 1)
    // off cayley with 4/5 probability, zero perf cost.
    stage1_kernel<<<dim3(64, 256), 64, S1_SMEM>>>(x, 0);
    stage1_kernel<<<dim3(64, 256), 64, S1_SMEM>>>(x, 256);
    stage2_kernel<<<dim3(16, 64), 256, S2_SMEM>>>(y, 0);
    stage2_kernel<<<dim3(16, 64), 256, S2_SMEM>>>(y, 64);
}

// round 16
// speedup vs baseline: 1.1995x; 1.1995x over previous
#include <cuda_runtime.h>
#include <cuda_fp16.h>

// ---------------------------------------------------------------------------
// GSOrthogonal round 16: stage2 rebuilt — per-warp all-4-l accumulators make
// the l-gather register-resident (no os smem, 1 barrier, no W-frag hoist ->
// ~96 regs). Stage1 reverted to round-14 form. Cayley unchanged.
//  stage1: g_t[l][r][b] = sum_p Rq[r][l][p] x[b][r*64+p]
//  stage2: y[b][s*64+l] = sum_r Lq[l][s][r] t[l][r][b]
// ---------------------------------------------------------------------------

__device__ __half g_Lq[64 * 64 * 64];
__device__ __half g_Rq[64 * 64 * 64];
__device__ __half g_t[(size_t)4096 * 16384];     // [l][r][b] fp16

__device__ __forceinline__ unsigned smem_u32(const void* p) {
    unsigned a;
    asm("{ .reg .u64 t; cvta.to.shared.u64 t, %1; cvt.u32.u64 %0, t; }"
        : "=r"(a) : "l"(p));
    return a;
}

#define SWZ(o) ((o) ^ (((o) >> 3) & 0x70u))

#define LDSM4(r0, r1, r2, r3, addr)                                           \
    asm volatile("ldmatrix.sync.aligned.m8n8.x4.shared.b16 {%0,%1,%2,%3},[%4];" \
        : "=r"(r0), "=r"(r1), "=r"(r2), "=r"(r3) : "r"(addr))
#define LDSM4T(r0, r1, r2, r3, addr)                                          \
    asm volatile("ldmatrix.sync.aligned.m8n8.x4.trans.shared.b16 {%0,%1,%2,%3},[%4];" \
        : "=r"(r0), "=r"(r1), "=r"(r2), "=r"(r3) : "r"(addr))
#define MMAF(d, a, b0, b1)                                                    \
    asm volatile("mma.sync.aligned.m16n8k16.row.col.f32.f16.f16.f32 "         \
        "{%0,%1,%2,%3},{%4,%5,%6,%7},{%8,%9},{%0,%1,%2,%3};"                  \
        : "+f"((d)[0]), "+f"((d)[1]), "+f"((d)[2]), "+f"((d)[3])              \
        : "r"((a)[0]), "r"((a)[1]), "r"((a)[2]), "r"((a)[3]), "r"(b0), "r"(b1))

__device__ __forceinline__ unsigned pack2h(__half a, __half b) {
    return (unsigned)__half_as_ushort(a) | ((unsigned)__half_as_ushort(b) << 16);
}

// ---------------- Cayley: scale-free GJ inverse, register-blocked -----------
#define CLD 68
__global__ __launch_bounds__(32) void cayley_kernel(
    const float* __restrict__ Lin, const float* __restrict__ Rin) {
    __shared__ float C[64 * CLD];
    const int blk = blockIdx.x;
    const float* A = blk < 64 ? Lin + blk * 4096 : Rin + (blk - 64) * 4096;
    __half* Q = blk < 64 ? g_Lq + blk * 4096 : g_Rq + (blk - 64) * 4096;
    const int lane = threadIdx.x;
    const int r0 = lane, r1 = lane + 32;

    for (int e = lane; e < 4096; e += 32) {
        int i = e >> 6, j = e & 63;
        C[i * CLD + j] = ((i == j) ? 1.0f : 0.0f)
                       + 0.5f * (A[i * 64 + j] - A[j * 64 + i]);
    }
    __syncwarp();

    for (int k = 0; k < 64; k++) {
        float piv = __fdividef(1.0f, C[k * CLD + k]);
        float f0 = C[r0 * CLD + k] * piv;
        float f1 = C[r1 * CLD + k] * piv;
        bool u0 = (r0 != k), u1 = (r1 != k);
        __syncwarp();
        #pragma unroll
        for (int h = 0; h < 2; h++) {
            const float4* p4 = (const float4*)(C + k * CLD) + h * 8;
            float4* m0 = (float4*)(C + r0 * CLD) + h * 8;
            float4* m1 = (float4*)(C + r1 * CLD) + h * 8;
            float4 p[8], a[8], b[8];
            #pragma unroll
            for (int c = 0; c < 8; c++) p[c] = p4[c];
            #pragma unroll
            for (int c = 0; c < 8; c++) a[c] = m0[c];
            #pragma unroll
            for (int c = 0; c < 8; c++) b[c] = m1[c];
            #pragma unroll
            for (int c = 0; c < 8; c++) {
                a[c].x -= f0 * p[c].x; a[c].y -= f0 * p[c].y;
                a[c].z -= f0 * p[c].z; a[c].w -= f0 * p[c].w;
                b[c].x -= f1 * p[c].x; b[c].y -= f1 * p[c].y;
                b[c].z -= f1 * p[c].z; b[c].w -= f1 * p[c].w;
            }
            if (u0) {
                #pragma unroll
                for (int c = 0; c < 8; c++) m0[c] = a[c];
            }
            if (u1) {
                #pragma unroll
                for (int c = 0; c < 8; c++) m1[c] = b[c];
            }
        }
        if (u0) C[r0 * CLD + k] = -f0;
        else  { C[r0 * CLD + k] = 1.0f; C[r0 * CLD + 64] = piv; }
        if (u1) C[r1 * CLD + k] = -f1;
        else  { C[r1 * CLD + k] = 1.0f; C[r1 * CLD + 64] = piv; }
        __syncwarp();
    }

    for (int e = lane; e < 4096; e += 32) {
        int a = e >> 6, b = e & 63;
        float v = 2.0f * C[b * CLD + 64] * C[b * CLD + a] - (a == b ? 1.0f : 0.0f);
        Q[e] = __float2half_rn(v);
    }
}

// ---------------- Stage 1: round-14 form (4 b-tiles, coalesced epilogue) ----
#define S1_A   0
#define S1_BH  16384
#define S1_OS  24576
#define S1_SMEM (24576 + 64 * 136 * 2)        // 41984
#define S1_TILES 4

__global__ __launch_bounds__(256, 2) void stage1_kernel(const float* __restrict__ x) {
    extern __shared__ char sm[];
    const unsigned sb = smem_u32(sm);
    __half* osp = (__half*)(sm + S1_OS);
    const int tid = threadIdx.x, wid = tid >> 5, lane = tid & 31;
    const int rblk = blockIdx.x;
    const long bbase = (long)blockIdx.y * (128 * S1_TILES);

    const int wm = wid & 3, wn = wid >> 2;
    const int M0 = wm * 32, N0 = wn * 32;
    const int g = lane >> 2, t2 = (lane & 3) << 1;

    #pragma unroll
    for (int q = 0; q < 4; q++) {
        int f = q * 256 + tid;
        int row = f >> 4, c4 = f & 15;
        uint2 u = *(const uint2*)(g_Rq + (size_t)rblk * 4096 + f * 4);
        *(uint2*)(sm + S1_BH + SWZ((unsigned)(row * 128 + c4 * 8))) = u;
    }
    uint2 xbuf[8];
    #pragma unroll
    for (int q = 0; q < 8; q++) {
        int f = q * 256 + tid;
        int row = f >> 4, p4 = f & 15;
        float4 v = *(const float4*)(x + (bbase + row) * 4096 + rblk * 64 + p4 * 4);
        xbuf[q] = make_uint2(pack2h(__float2half_rn(v.x), __float2half_rn(v.y)),
                             pack2h(__float2half_rn(v.z), __float2half_rn(v.w)));
    }
    __syncthreads();

    unsigned bfr[4][2][4];
    #pragma unroll
    for (int kk = 0; kk < 4; kk++)
        #pragma unroll
        for (int nh = 0; nh < 2; nh++) {
            unsigned row = N0 + nh * 16 + (lane & 7) + ((lane >> 4) << 3);
            unsigned ph = SWZ(row * 128 + kk * 32 + (((lane >> 3) & 1) << 4));
            LDSM4(bfr[kk][nh][0], bfr[kk][nh][1], bfr[kk][nh][2], bfr[kk][nh][3],
                  sb + S1_BH + ph);
        }

    for (int tb = 0; tb < S1_TILES; tb++) {
        const long b0 = bbase + tb * 128;
        #pragma unroll
        for (int q = 0; q < 8; q++) {
            int f = q * 256 + tid;
            int row = f >> 4, p4 = f & 15;
            *(uint2*)(sm + S1_A + SWZ((unsigned)(row * 128 + p4 * 8))) = xbuf[q];
        }
        __syncthreads();
        if (tb + 1 < S1_TILES) {
            #pragma unroll
            for (int q = 0; q < 8; q++) {
                int f = q * 256 + tid;
                int row = f >> 4, p4 = f & 15;
                float4 v = *(const float4*)(x + (b0 + 128 + row) * 4096
                                              + rblk * 64 + p4 * 4);
                xbuf[q] = make_uint2(
                    pack2h(__float2half_rn(v.x), __float2half_rn(v.y)),
                    pack2h(__float2half_rn(v.z), __float2half_rn(v.w)));
            }
        }

        float acc[2][4][4] = {};
        #pragma unroll
        for (int kk = 0; kk < 4; kk++) {
            unsigned ah[2][4];
            #pragma unroll
            for (int mt = 0; mt < 2; mt++) {
                unsigned row = M0 + mt * 16 + (lane & 15);
                unsigned ph = SWZ(row * 128 + kk * 32 + ((lane >> 4) << 4));
                LDSM4(ah[mt][0], ah[mt][1], ah[mt][2], ah[mt][3], sb + S1_A + ph);
            }
            #pragma unroll
            for (int mt = 0; mt < 2; mt++)
                #pragma unroll
                for (int nh = 0; nh < 2; nh++) {
                    MMAF(acc[mt][nh * 2 + 0], ah[mt], bfr[kk][nh][0], bfr[kk][nh][1]);
                    MMAF(acc[mt][nh * 2 + 1], ah[mt], bfr[kk][nh][2], bfr[kk][nh][3]);
                }
        }

        #pragma unroll
        for (int mt = 0; mt < 2; mt++) {
            const int bb = M0 + mt * 16 + g;
            #pragma unroll
            for (int nt = 0; nt < 4; nt++) {
                int l0 = N0 + nt * 8 + t2;
                osp[l0 * 136 + bb]             = __float2half_rn(acc[mt][nt][0]);
                osp[(l0 + 1) * 136 + bb]       = __float2half_rn(acc[mt][nt][1]);
                osp[l0 * 136 + bb + 8]         = __float2half_rn(acc[mt][nt][2]);
                osp[(l0 + 1) * 136 + bb + 8]   = __float2half_rn(acc[mt][nt][3]);
            }
        }
        __syncthreads();

        #pragma unroll
        for (int q = 0; q < 8; q++) {
            int e = q * 256 + tid;
            int l = e >> 5, b4 = e & 31;
            uint2 v = *(const uint2*)((const char*)osp + l * 272 + b4 * 8);
            *(uint2*)(g_t + ((size_t)l * 64 + rblk) * 16384 + b0 + b4 * 4) = v;
        }
        __syncthreads();
    }
}

// ---------------- Stage 2: one-shot 64b x 64s x 4l, register l-gather -------
// smem: A planes 4x8KB @0; W planes 4x8KB @32768. One barrier. No os.
#define T2_A   0
#define T2_W   32768
#define T2_SMEM 65536

__global__ __launch_bounds__(256) void stage2_kernel(float* __restrict__ y) {
    extern __shared__ char sm[];
    const unsigned sb = smem_u32(sm);
    const int tid = threadIdx.x, wid = tid >> 5, lane = tid & 31;
    const int lg = blockIdx.x;                    // 0..15
    const long b0 = (long)blockIdx.y * 64;        // grid.y = 256

    // A planes: At[pl][r][b] fp16 (k-major), 128B rows, swizzled
    #pragma unroll
    for (int q = 0; q < 16; q++) {
        int f = q * 256 + tid;                    // 0..4095
        int pl = f >> 10, e = f & 1023;
        int r = e >> 4, b4 = e & 15;
        uint2 u = *(const uint2*)(g_t + ((size_t)(lg * 4 + pl) * 64 + r) * 16384
                                      + b0 + b4 * 4);
        *(uint2*)(sm + T2_A + pl * 8192 + SWZ((unsigned)(r * 128 + b4 * 8))) = u;
    }
    // W planes: W[pl][s][r] fp16
    #pragma unroll
    for (int q = 0; q < 16; q++) {
        int f = q * 256 + tid;
        int pl = f >> 10, e = f & 1023;
        int r = e >> 4, b4 = e & 15;
        uint2 u = *(const uint2*)(g_Lq + (size_t)(lg * 4 + pl) * 4096 + e * 4);
        *(uint2*)(sm + T2_W + pl * 8192 + SWZ((unsigned)(r * 128 + b4 * 8))) = u;
    }
    __syncthreads();

    // warp: m16 (b) rows M0; two n16 (s) subtiles at Nbase and Nbase+32
    const int M0 = (wid & 3) * 16;
    const int Nbase = (wid >> 2) * 16;
    float acc[2][4][2][4] = {};                   // [sub][pl][nt][c]

    #pragma unroll
    for (int pl = 0; pl < 4; pl++) {
        #pragma unroll
        for (int kk = 0; kk < 4; kk++) {
            unsigned a4[4];
            {   // A m16 x k16 via ldmatrix.trans from At[r][b]
                unsigned row = kk * 16 + (lane & 7) + ((lane >> 4) << 3);
                unsigned cb = (unsigned)(M0 + (((lane >> 3) & 1) << 3)) * 2;
                LDSM4T(a4[0], a4[1], a4[2], a4[3],
                       sb + T2_A + pl * 8192 + SWZ(row * 128 + cb));
            }
            #pragma unroll
            for (int sub = 0; sub < 2; sub++) {
                unsigned N0 = Nbase + sub * 32;
                unsigned wrow = N0 + (lane & 7) + ((lane >> 4) << 3);
                unsigned wph = SWZ(wrow * 128 + kk * 32 + (((lane >> 3) & 1) << 4));
                unsigned w4[4];
                LDSM4(w4[0], w4[1], w4[2], w4[3], sb + T2_W + pl * 8192 + wph);
                MMAF(acc[sub][pl][0], a4, w4[0], w4[1]);
                MMAF(acc[sub][pl][1], a4, w4[2], w4[3]);
            }
        }
    }

    // epilogue: y[b][s*64 + lg*4 + pl] — float4 over pl, pure registers
    const int g = lane >> 2, t2 = (lane & 3) << 1;
    #pragma unroll
    for (int sub = 0; sub < 2; sub++)
        #pragma unroll
        for (int nt = 0; nt < 2; nt++) {
            int s0 = Nbase + sub * 32 + nt * 8 + t2;
            float* r0p = y + (b0 + M0 + g) * 4096 + (size_t)s0 * 64 + lg * 4;
            float* r1p = r0p + 8 * 4096;
            *(float4*)r0p = make_float4(acc[sub][0][nt][0], acc[sub][1][nt][0],
                                        acc[sub][2][nt][0], acc[sub][3][nt][0]);
            *(float4*)(r0p + 64) = make_float4(acc[sub][0][nt][1], acc[sub][1][nt][1],
                                               acc[sub][2][nt][1], acc[sub][3][nt][1]);
            *(float4*)r1p = make_float4(acc[sub][0][nt][2], acc[sub][1][nt][2],
                                        acc[sub][2][nt][2], acc[sub][3][nt][2]);
            *(float4*)(r1p + 64) = make_float4(acc[sub][0][nt][3], acc[sub][1][nt][3],
                                               acc[sub][2][nt][3], acc[sub][3][nt][3]);
        }
}

// ---------------------------------------------------------------------------
extern "C" void kernel_launch(void* const* d_in, const int* in_sizes, int n_in,
                              void* d_out, int out_size) {
    const float* x = (const float*)d_in[0];
    const float* L = (const float*)d_in[1];
    const float* R = (const float*)d_in[2];
    float* y = (float*)d_out;

    cudaFuncSetAttribute(stage1_kernel,
                         cudaFuncAttributeMaxDynamicSharedMemorySize, S1_SMEM);
    cudaFuncSetAttribute(stage2_kernel,
                         cudaFuncAttributeMaxDynamicSharedMemorySize, T2_SMEM);

    cayley_kernel<<<128, 32>>>(L, R);
    stage1_kernel<<<dim3(64, 32), 256, S1_SMEM>>>(x);
    stage2_kernel<<<dim3(16, 256), 256, T2_SMEM>>>(y);
}

// round 17
// speedup vs baseline: 1.2930x; 1.0780x over previous
#include <cuda_runtime.h>
#include <cuda_fp16.h>

// ---------------------------------------------------------------------------
// GSOrthogonal round 17: stage1 rebuilt with the stage2-winning recipe —
// one-shot tile per CTA, 2 barriers, no register hoists, higher occupancy.
// Stage2 (register l-gather) + cayley unchanged from round 16.
//  stage1: g_t[l][r][b] = sum_p Rq[r][l][p] x[b][r*64+p]
//  stage2: y[b][s*64+l] = sum_r Lq[l][s][r] t[l][r][b]
// ---------------------------------------------------------------------------

__device__ __half g_Lq[64 * 64 * 64];
__device__ __half g_Rq[64 * 64 * 64];
__device__ __half g_t[(size_t)4096 * 16384];     // [l][r][b] fp16

__device__ __forceinline__ unsigned smem_u32(const void* p) {
    unsigned a;
    asm("{ .reg .u64 t; cvta.to.shared.u64 t, %1; cvt.u32.u64 %0, t; }"
        : "=r"(a) : "l"(p));
    return a;
}

#define SWZ(o) ((o) ^ (((o) >> 3) & 0x70u))

#define LDSM4(r0, r1, r2, r3, addr)                                           \
    asm volatile("ldmatrix.sync.aligned.m8n8.x4.shared.b16 {%0,%1,%2,%3},[%4];" \
        : "=r"(r0), "=r"(r1), "=r"(r2), "=r"(r3) : "r"(addr))
#define LDSM4T(r0, r1, r2, r3, addr)                                          \
    asm volatile("ldmatrix.sync.aligned.m8n8.x4.trans.shared.b16 {%0,%1,%2,%3},[%4];" \
        : "=r"(r0), "=r"(r1), "=r"(r2), "=r"(r3) : "r"(addr))
#define MMAF(d, a, b0, b1)                                                    \
    asm volatile("mma.sync.aligned.m16n8k16.row.col.f32.f16.f16.f32 "         \
        "{%0,%1,%2,%3},{%4,%5,%6,%7},{%8,%9},{%0,%1,%2,%3};"                  \
        : "+f"((d)[0]), "+f"((d)[1]), "+f"((d)[2]), "+f"((d)[3])              \
        : "r"((a)[0]), "r"((a)[1]), "r"((a)[2]), "r"((a)[3]), "r"(b0), "r"(b1))

__device__ __forceinline__ unsigned pack2h(__half a, __half b) {
    return (unsigned)__half_as_ushort(a) | ((unsigned)__half_as_ushort(b) << 16);
}

// ---------------- Cayley: scale-free GJ inverse, register-blocked -----------
#define CLD 68
__global__ __launch_bounds__(32) void cayley_kernel(
    const float* __restrict__ Lin, const float* __restrict__ Rin) {
    __shared__ float C[64 * CLD];
    const int blk = blockIdx.x;
    const float* A = blk < 64 ? Lin + blk * 4096 : Rin + (blk - 64) * 4096;
    __half* Q = blk < 64 ? g_Lq + blk * 4096 : g_Rq + (blk - 64) * 4096;
    const int lane = threadIdx.x;
    const int r0 = lane, r1 = lane + 32;

    for (int e = lane; e < 4096; e += 32) {
        int i = e >> 6, j = e & 63;
        C[i * CLD + j] = ((i == j) ? 1.0f : 0.0f)
                       + 0.5f * (A[i * 64 + j] - A[j * 64 + i]);
    }
    __syncwarp();

    for (int k = 0; k < 64; k++) {
        float piv = __fdividef(1.0f, C[k * CLD + k]);
        float f0 = C[r0 * CLD + k] * piv;
        float f1 = C[r1 * CLD + k] * piv;
        bool u0 = (r0 != k), u1 = (r1 != k);
        __syncwarp();
        #pragma unroll
        for (int h = 0; h < 2; h++) {
            const float4* p4 = (const float4*)(C + k * CLD) + h * 8;
            float4* m0 = (float4*)(C + r0 * CLD) + h * 8;
            float4* m1 = (float4*)(C + r1 * CLD) + h * 8;
            float4 p[8], a[8], b[8];
            #pragma unroll
            for (int c = 0; c < 8; c++) p[c] = p4[c];
            #pragma unroll
            for (int c = 0; c < 8; c++) a[c] = m0[c];
            #pragma unroll
            for (int c = 0; c < 8; c++) b[c] = m1[c];
            #pragma unroll
            for (int c = 0; c < 8; c++) {
                a[c].x -= f0 * p[c].x; a[c].y -= f0 * p[c].y;
                a[c].z -= f0 * p[c].z; a[c].w -= f0 * p[c].w;
                b[c].x -= f1 * p[c].x; b[c].y -= f1 * p[c].y;
                b[c].z -= f1 * p[c].z; b[c].w -= f1 * p[c].w;
            }
            if (u0) {
                #pragma unroll
                for (int c = 0; c < 8; c++) m0[c] = a[c];
            }
            if (u1) {
                #pragma unroll
                for (int c = 0; c < 8; c++) m1[c] = b[c];
            }
        }
        if (u0) C[r0 * CLD + k] = -f0;
        else  { C[r0 * CLD + k] = 1.0f; C[r0 * CLD + 64] = piv; }
        if (u1) C[r1 * CLD + k] = -f1;
        else  { C[r1 * CLD + k] = 1.0f; C[r1 * CLD + 64] = piv; }
        __syncwarp();
    }

    for (int e = lane; e < 4096; e += 32) {
        int a = e >> 6, b = e & 63;
        float v = 2.0f * C[b * CLD + 64] * C[b * CLD + a] - (a == b ? 1.0f : 0.0f);
        Q[e] = __float2half_rn(v);
    }
}

// ---------------- Stage 1: one-shot 128b x 64l x 64p, 2 barriers ------------
// smem: A 16KB @0; B 8KB @16384; osp [64 l][136 halves] @24576 -> 41984 B
#define S1_A   0
#define S1_BH  16384
#define S1_OS  24576
#define S1_SMEM (24576 + 64 * 136 * 2)        // 41984

__global__ __launch_bounds__(256) void stage1_kernel(const float* __restrict__ x) {
    extern __shared__ char sm[];
    const unsigned sb = smem_u32(sm);
    __half* osp = (__half*)(sm + S1_OS);
    const int tid = threadIdx.x, wid = tid >> 5, lane = tid & 31;
    const int rblk = blockIdx.x;
    const long b0 = (long)blockIdx.y * 128;

    // B = Rq[rblk] (L2-hot, redundant across b-tiles)
    #pragma unroll
    for (int q = 0; q < 4; q++) {
        int f = q * 256 + tid;
        int row = f >> 4, c4 = f & 15;
        uint2 u = *(const uint2*)(g_Rq + (size_t)rblk * 4096 + f * 4);
        *(uint2*)(sm + S1_BH + SWZ((unsigned)(row * 128 + c4 * 8))) = u;
    }
    // A = x tile 128x64, converted to fp16
    #pragma unroll
    for (int q = 0; q < 8; q++) {
        int f = q * 256 + tid;
        int row = f >> 4, p4 = f & 15;
        float4 v = *(const float4*)(x + (b0 + row) * 4096 + rblk * 64 + p4 * 4);
        uint2 h = make_uint2(pack2h(__float2half_rn(v.x), __float2half_rn(v.y)),
                             pack2h(__float2half_rn(v.z), __float2half_rn(v.w)));
        *(uint2*)(sm + S1_A + SWZ((unsigned)(row * 128 + p4 * 8))) = h;
    }
    __syncthreads();

    const int wm = wid & 3, wn = wid >> 2;
    const int M0 = wm * 32, N0 = wn * 32;
    const int g = lane >> 2, t2 = (lane & 3) << 1;

    float acc[2][4][4] = {};
    #pragma unroll
    for (int kk = 0; kk < 4; kk++) {
        unsigned ah[2][4];
        #pragma unroll
        for (int mt = 0; mt < 2; mt++) {
            unsigned row = M0 + mt * 16 + (lane & 15);
            unsigned ph = SWZ(row * 128 + kk * 32 + ((lane >> 4) << 4));
            LDSM4(ah[mt][0], ah[mt][1], ah[mt][2], ah[mt][3], sb + S1_A + ph);
        }
        #pragma unroll
        for (int nh = 0; nh < 2; nh++) {
            unsigned row = N0 + nh * 16 + (lane & 7) + ((lane >> 4) << 3);
            unsigned ph = SWZ(row * 128 + kk * 32 + (((lane >> 3) & 1) << 4));
            unsigned bh[4];
            LDSM4(bh[0], bh[1], bh[2], bh[3], sb + S1_BH + ph);
            #pragma unroll
            for (int mt = 0; mt < 2; mt++) {
                MMAF(acc[mt][nh * 2 + 0], ah[mt], bh[0], bh[1]);
                MMAF(acc[mt][nh * 2 + 1], ah[mt], bh[2], bh[3]);
            }
        }
    }

    // stage acc -> osp[l][b] (halves, row pitch 136)
    #pragma unroll
    for (int mt = 0; mt < 2; mt++) {
        const int bb = M0 + mt * 16 + g;
        #pragma unroll
        for (int nt = 0; nt < 4; nt++) {
            int l0 = N0 + nt * 8 + t2;
            osp[l0 * 136 + bb]           = __float2half_rn(acc[mt][nt][0]);
            osp[(l0 + 1) * 136 + bb]     = __float2half_rn(acc[mt][nt][1]);
            osp[l0 * 136 + bb + 8]       = __float2half_rn(acc[mt][nt][2]);
            osp[(l0 + 1) * 136 + bb + 8] = __float2half_rn(acc[mt][nt][3]);
        }
    }
    __syncthreads();

    // coalesced write: 256B contiguous per instruction
    #pragma unroll
    for (int q = 0; q < 8; q++) {
        int e = q * 256 + tid;                // 0..2047 uint2 units
        int l = e >> 5, b4 = e & 31;
        uint2 v = *(const uint2*)((const char*)osp + l * 272 + b4 * 8);
        *(uint2*)(g_t + ((size_t)l * 64 + rblk) * 16384 + b0 + b4 * 4) = v;
    }
}

// ---------------- Stage 2: one-shot 64b x 64s x 4l, register l-gather -------
#define T2_A   0
#define T2_W   32768
#define T2_SMEM 65536

__global__ __launch_bounds__(256) void stage2_kernel(float* __restrict__ y) {
    extern __shared__ char sm[];
    const unsigned sb = smem_u32(sm);
    const int tid = threadIdx.x, wid = tid >> 5, lane = tid & 31;
    const int lg = blockIdx.x;                    // 0..15
    const long b0 = (long)blockIdx.y * 64;        // grid.y = 256

    #pragma unroll
    for (int q = 0; q < 16; q++) {
        int f = q * 256 + tid;                    // 0..4095
        int pl = f >> 10, e = f & 1023;
        int r = e >> 4, b4 = e & 15;
        uint2 u = *(const uint2*)(g_t + ((size_t)(lg * 4 + pl) * 64 + r) * 16384
                                      + b0 + b4 * 4);
        *(uint2*)(sm + T2_A + pl * 8192 + SWZ((unsigned)(r * 128 + b4 * 8))) = u;
    }
    #pragma unroll
    for (int q = 0; q < 16; q++) {
        int f = q * 256 + tid;
        int pl = f >> 10, e = f & 1023;
        int r = e >> 4, b4 = e & 15;
        uint2 u = *(const uint2*)(g_Lq + (size_t)(lg * 4 + pl) * 4096 + e * 4);
        *(uint2*)(sm + T2_W + pl * 8192 + SWZ((unsigned)(r * 128 + b4 * 8))) = u;
    }
    __syncthreads();

    const int M0 = (wid & 3) * 16;
    const int Nbase = (wid >> 2) * 16;
    float acc[2][4][2][4] = {};                   // [sub][pl][nt][c]

    #pragma unroll
    for (int pl = 0; pl < 4; pl++) {
        #pragma unroll
        for (int kk = 0; kk < 4; kk++) {
            unsigned a4[4];
            {
                unsigned row = kk * 16 + (lane & 7) + ((lane >> 4) << 3);
                unsigned cb = (unsigned)(M0 + (((lane >> 3) & 1) << 3)) * 2;
                LDSM4T(a4[0], a4[1], a4[2], a4[3],
                       sb + T2_A + pl * 8192 + SWZ(row * 128 + cb));
            }
            #pragma unroll
            for (int sub = 0; sub < 2; sub++) {
                unsigned N0 = Nbase + sub * 32;
                unsigned wrow = N0 + (lane & 7) + ((lane >> 4) << 3);
                unsigned wph = SWZ(wrow * 128 + kk * 32 + (((lane >> 3) & 1) << 4));
                unsigned w4[4];
                LDSM4(w4[0], w4[1], w4[2], w4[3], sb + T2_W + pl * 8192 + wph);
                MMAF(acc[sub][pl][0], a4, w4[0], w4[1]);
                MMAF(acc[sub][pl][1], a4, w4[2], w4[3]);
            }
        }
    }

    const int g = lane >> 2, t2 = (lane & 3) << 1;
    #pragma unroll
    for (int sub = 0; sub < 2; sub++)
        #pragma unroll
        for (int nt = 0; nt < 2; nt++) {
            int s0 = Nbase + sub * 32 + nt * 8 + t2;
            float* r0p = y + (b0 + M0 + g) * 4096 + (size_t)s0 * 64 + lg * 4;
            float* r1p = r0p + 8 * 4096;
            *(float4*)r0p = make_float4(acc[sub][0][nt][0], acc[sub][1][nt][0],
                                        acc[sub][2][nt][0], acc[sub][3][nt][0]);
            *(float4*)(r0p + 64) = make_float4(acc[sub][0][nt][1], acc[sub][1][nt][1],
                                               acc[sub][2][nt][1], acc[sub][3][nt][1]);
            *(float4*)r1p = make_float4(acc[sub][0][nt][2], acc[sub][1][nt][2],
                                        acc[sub][2][nt][2], acc[sub][3][nt][2]);
            *(float4*)(r1p + 64) = make_float4(acc[sub][0][nt][3], acc[sub][1][nt][3],
                                               acc[sub][2][nt][3], acc[sub][3][nt][3]);
        }
}

// ---------------------------------------------------------------------------
extern "C" void kernel_launch(void* const* d_in, const int* in_sizes, int n_in,
                              void* d_out, int out_size) {
    const float* x = (const float*)d_in[0];
    const float* L = (const float*)d_in[1];
    const float* R = (const float*)d_in[2];
    float* y = (float*)d_out;

    cudaFuncSetAttribute(stage1_kernel,
                         cudaFuncAttributeMaxDynamicSharedMemorySize, S1_SMEM);
    cudaFuncSetAttribute(stage2_kernel,
                         cudaFuncAttributeMaxDynamicSharedMemorySize, T2_SMEM);

    cayley_kernel<<<128, 32>>>(L, R);
    stage1_kernel<<<dim3(64, 128), 256, S1_SMEM>>>(x);
    stage2_kernel<<<dim3(16, 256), 256, T2_SMEM>>>(y);
}